// round 7
// baseline (speedup 1.0000x reference)
#include <cuda_runtime.h>
#include <cuda_bf16.h>
#include <cstdint>
#include <cstddef>

// Problem constants
#define BB 4
#define CC 128
#define NN 4096      // H*W
#define CQ 16
#define TQ 128       // queries per CTA
#define TK 128       // keys per tile
#define NTILES (NN / TK)   // 32

// ---------------------------------------------------------------------------
// Device scratch (bf16 QKV staged between kernels)
// ---------------------------------------------------------------------------
__device__ __align__(16) __nv_bfloat16 g_qb[(size_t)BB * NN * CQ];  // [b][n][cq]
__device__ __align__(16) __nv_bfloat16 g_kb[(size_t)BB * NN * CQ];  // [b][n][cq]
__device__ __align__(16) __nv_bfloat16 g_vb[(size_t)BB * CC * NN];  // [b][c][n]

// ---------------------------------------------------------------------------
// Helpers
// ---------------------------------------------------------------------------
__device__ __forceinline__ uint32_t smem_u32(const void* p) {
    uint32_t a;
    asm("{ .reg .u64 t; cvta.to.shared.u64 t, %1; cvt.u32.u64 %0, t; }"
        : "=r"(a) : "l"(p));
    return a;
}
// pack two fp32 -> bf16x2 (lo in low half)
__device__ __forceinline__ uint32_t pack_bf2(float lo, float hi) {
    uint32_t r;
    asm("cvt.rn.satfinite.bf16x2.f32 %0, %1, %2;" : "=r"(r) : "f"(hi), "f"(lo));
    return r;
}
__device__ __forceinline__ void cp16(uint32_t dst, const void* src) {
    asm volatile("cp.async.cg.shared.global [%0], [%1], 16;"
                 :: "r"(dst), "l"(src));
}
#define CP_COMMIT() asm volatile("cp.async.commit_group;" ::: "memory")
#define CP_WAIT(n)  asm volatile("cp.async.wait_group %0;" :: "n"(n) : "memory")

// mma.m16n8k16 bf16 -> fp32
__device__ __forceinline__ void mma16816(
    float* d,
    uint32_t a0, uint32_t a1, uint32_t a2, uint32_t a3,
    uint32_t b0, uint32_t b1,
    float c0, float c1, float c2, float c3)
{
    asm volatile(
        "mma.sync.aligned.m16n8k16.row.col.f32.bf16.bf16.f32 "
        "{%0,%1,%2,%3}, {%4,%5,%6,%7}, {%8,%9}, {%10,%11,%12,%13};"
        : "=f"(d[0]), "=f"(d[1]), "=f"(d[2]), "=f"(d[3])
        : "r"(a0), "r"(a1), "r"(a2), "r"(a3),
          "r"(b0), "r"(b1),
          "f"(c0), "f"(c1), "f"(c2), "f"(c3));
}

// ---------------------------------------------------------------------------
// Kernel 1: Q/K 1x1 conv -> bf16 [b][n][16].
// 128 n per CTA, 2 threads per n (channel split), smem reduction.
// grid (32, 4), block 256.
// ---------------------------------------------------------------------------
__global__ void __launch_bounds__(256) qk_kernel(
    const float* __restrict__ x,
    const float* __restrict__ wq, const float* __restrict__ bq,
    const float* __restrict__ wk, const float* __restrict__ bk)
{
    __shared__ float wqs[CQ * CC];   // transposed [c][r]
    __shared__ float wks[CQ * CC];
    __shared__ float red[128 * 33];

    const int tid = threadIdx.x;
    for (int i = tid; i < CQ * CC; i += 256) {
        int r = i >> 7, c = i & 127;
        wqs[c * 16 + r] = wq[i];
        wks[c * 16 + r] = wk[i];
    }
    __syncthreads();

    const int b    = blockIdx.y;
    const int nl   = tid & 127;
    const int half = tid >> 7;
    const int n    = blockIdx.x * 128 + nl;
    const int c0   = half * 64;

    float qa[16], ka[16];
#pragma unroll
    for (int r = 0; r < 16; ++r) {
        qa[r] = half ? 0.f : bq[r];
        ka[r] = half ? 0.f : bk[r];
    }

    const float* xp = x + (size_t)b * CC * NN + n;
#pragma unroll 4
    for (int cc = 0; cc < 64; ++cc) {
        const int c = c0 + cc;
        const float xv = xp[(size_t)c * NN];
        const float4* q4 = (const float4*)(wqs + c * 16);
        const float4* k4 = (const float4*)(wks + c * 16);
#pragma unroll
        for (int j = 0; j < 4; ++j) {
            float4 w = q4[j];
            qa[4*j+0] += w.x * xv; qa[4*j+1] += w.y * xv;
            qa[4*j+2] += w.z * xv; qa[4*j+3] += w.w * xv;
            w = k4[j];
            ka[4*j+0] += w.x * xv; ka[4*j+1] += w.y * xv;
            ka[4*j+2] += w.z * xv; ka[4*j+3] += w.w * xv;
        }
    }

    if (half) {
#pragma unroll
        for (int j = 0; j < 16; ++j) {
            red[nl * 33 + j]      = qa[j];
            red[nl * 33 + 16 + j] = ka[j];
        }
    }
    __syncthreads();
    if (!half) {
#pragma unroll
        for (int j = 0; j < 16; ++j) {
            qa[j] += red[nl * 33 + j];
            ka[j] += red[nl * 33 + 16 + j];
        }
        uint32_t qp[8], kp[8];
#pragma unroll
        for (int j = 0; j < 8; ++j) {
            qp[j] = pack_bf2(qa[2*j], qa[2*j+1]);
            kp[j] = pack_bf2(ka[2*j], ka[2*j+1]);
        }
        uint4* qd = (uint4*)((char*)g_qb + ((size_t)b * NN + n) * 32);
        uint4* kd = (uint4*)((char*)g_kb + ((size_t)b * NN + n) * 32);
        qd[0] = make_uint4(qp[0], qp[1], qp[2], qp[3]);
        qd[1] = make_uint4(qp[4], qp[5], qp[6], qp[7]);
        kd[0] = make_uint4(kp[0], kp[1], kp[2], kp[3]);
        kd[1] = make_uint4(kp[4], kp[5], kp[6], kp[7]);
    }
}

// ---------------------------------------------------------------------------
// Kernel 2: V 1x1 conv as smem-tiled GEMM.  out[128c x 128n] per CTA.
// W staged transposed once (pitch 132 -> 16B-aligned float4 rows; W reads are
// per-tj broadcasts so no conflicts possible), x double-buffered via cp.async
// in k-steps of 16. Thread (ti,tj) computes 8c x 8n.
// grid (32, 4), block 256. dyn smem = 128*132*4 + 2*16*128*4 = 83968 B.
// ---------------------------------------------------------------------------
#define WPITCH 132
#define VG_SMEM (128 * WPITCH * 4 + 2 * 16 * 128 * 4)

__global__ void __launch_bounds__(256, 1) v_kernel(
    const float* __restrict__ x,
    const float* __restrict__ wv, const float* __restrict__ bv)
{
    extern __shared__ float vsm[];
    float* w_st = vsm;                    // [128 k][WPITCH] transposed
    float* x_s  = vsm + 128 * WPITCH;     // [2][16][128]
    const uint32_t xsb = smem_u32(x_s);

    const int tid = threadIdx.x;
    const int b   = blockIdx.y;
    const int n0  = blockIdx.x * 128;
    const int ti  = tid & 15;             // n group
    const int tj  = tid >> 4;             // c group
    const int c0  = tj * 8;
    const int nb  = ti * 8;

    // stage W transposed: w_st[k][c] = wv[c][k]
    for (int i = tid; i < CC * CC; i += 256) {
        const int c = i >> 7, k = i & 127;
        w_st[k * WPITCH + c] = wv[i];
    }

    const float* xb = x + (size_t)b * CC * NN + n0;

    // stage x k-block 0
    {
#pragma unroll
        for (int it = 0; it < 2; ++it) {
            const int i = tid + it * 256;          // 512 chunks
            const int r = i >> 5, cc = (i & 31) * 4;
            cp16(xsb + (uint32_t)(r * 128 + cc) * 4,
                 xb + (size_t)r * NN + cc);
        }
    }
    CP_COMMIT();

    float acc[8][8];
#pragma unroll
    for (int j = 0; j < 8; ++j)
#pragma unroll
        for (int k = 0; k < 8; ++k) acc[j][k] = 0.f;

    for (int t = 0; t < 8; ++t) {
        if (t + 1 < 8) {
            const uint32_t dst = xsb + (uint32_t)(((t + 1) & 1) * 2048) * 4;
#pragma unroll
            for (int it = 0; it < 2; ++it) {
                const int i = tid + it * 256;
                const int r = i >> 5, cc = (i & 31) * 4;
                cp16(dst + (uint32_t)(r * 128 + cc) * 4,
                     xb + (size_t)(16 * (t + 1) + r) * NN + cc);
            }
            CP_COMMIT();
            CP_WAIT(1);
        } else {
            CP_WAIT(0);
        }
        __syncthreads();

        const float* xs = x_s + (t & 1) * 2048;
        const float* wk = w_st + 16 * t * WPITCH;
#pragma unroll
        for (int kk = 0; kk < 16; ++kk) {
            const float4 w0 = *(const float4*)(wk + kk * WPITCH + c0);
            const float4 w1 = *(const float4*)(wk + kk * WPITCH + c0 + 4);
            const float4 x0 = *(const float4*)(xs + kk * 128 + nb);
            const float4 x1 = *(const float4*)(xs + kk * 128 + nb + 4);
            const float wr[8] = {w0.x, w0.y, w0.z, w0.w, w1.x, w1.y, w1.z, w1.w};
            const float xr[8] = {x0.x, x0.y, x0.z, x0.w, x1.x, x1.y, x1.z, x1.w};
#pragma unroll
            for (int j = 0; j < 8; ++j)
#pragma unroll
                for (int k = 0; k < 8; ++k)
                    acc[j][k] += wr[j] * xr[k];
        }
        __syncthreads();
    }

    // epilogue: add bias, pack bf16, store [c][n]
#pragma unroll
    for (int j = 0; j < 8; ++j) {
        const float bb = bv[c0 + j];
        uint4 u;
        u.x = pack_bf2(acc[j][0] + bb, acc[j][1] + bb);
        u.y = pack_bf2(acc[j][2] + bb, acc[j][3] + bb);
        u.z = pack_bf2(acc[j][4] + bb, acc[j][5] + bb);
        u.w = pack_bf2(acc[j][6] + bb, acc[j][7] + bb);
        *(uint4*)((char*)g_vb + (((size_t)b * CC + c0 + j) * NN + n0 + nb) * 2) = u;
    }
}

// ---------------------------------------------------------------------------
// Kernel 3: HMMA flash attention, 4 warps x 32 queries.
// grid (32, 4), 128 threads; warp w owns queries [32w, 32w+32) (2 row blocks).
// smem: Q [128][48] 6144 | K0/K1 6144 | V0/V1 [128c][272] 34816 ea. 88064 B.
// ---------------------------------------------------------------------------
#define KPITCH 48
#define VPITCH 272
#define SM_Q   0
#define SM_K0  6144
#define SM_K1  12288
#define SM_V0  18432
#define SM_V1  (SM_V0 + 34816)
#define SM_TOTAL (SM_V1 + 34816)

__device__ __forceinline__ void issue_tile(
    uint32_t smb, const char* kg, const char* vg, int t, int buf, int tid)
{
    const uint32_t kdst = smb + (buf ? SM_K1 : SM_K0);
    const uint32_t vdst = smb + (buf ? SM_V1 : SM_V0);
    const int m0 = t * TK;
#pragma unroll
    for (int it = 0; it < 2; ++it) {   // K: 256 x 16B chunks
        const int i = tid + it * 128;
        const int n = i >> 1, h = i & 1;
        cp16(kdst + n * KPITCH + h * 16, kg + (size_t)(m0 + n) * 32 + h * 16);
    }
#pragma unroll
    for (int it = 0; it < 16; ++it) {  // V: 2048 x 16B chunks
        const int i = tid + it * 128;
        const int c = i >> 4, h = i & 15;
        cp16(vdst + c * VPITCH + h * 16,
             vg + (size_t)c * (NN * 2) + (size_t)m0 * 2 + h * 16);
    }
}

__global__ void __launch_bounds__(128, 1) attn_kernel(
    const float* __restrict__ x,
    const float* __restrict__ gamma,
    float* __restrict__ out)
{
    extern __shared__ char sm[];
    const uint32_t smb = smem_u32(sm);
    const int tid  = threadIdx.x;
    const int w    = tid >> 5;
    const int lane = tid & 31;
    const int p    = lane >> 2;
    const int q    = lane & 3;

    const int b  = blockIdx.y;
    const int n0 = blockIdx.x * TQ;

    const char* qg = (const char*)g_qb + ((size_t)b * NN + n0) * 32;
    const char* kg = (const char*)g_kb + (size_t)b * NN * 32;
    const char* vg = (const char*)g_vb + (size_t)b * CC * NN * 2;

    // ---- load Q tile (plain), issue K/V tile 0 ----
    {
        const int r = tid;   // 128 rows, 32B each
        *(uint4*)(sm + SM_Q + r * KPITCH)      = *(const uint4*)(qg + r * 32);
        *(uint4*)(sm + SM_Q + r * KPITCH + 16) = *(const uint4*)(qg + r * 32 + 16);
    }
    issue_tile(smb, kg, vg, 0, 0, tid);
    CP_COMMIT();
    __syncthreads();

    // ---- Q A-fragments for both row blocks ----
    uint32_t qa[2][4];
#pragma unroll
    for (int r = 0; r < 2; ++r) {
        const int row = 32 * w + 16 * r + p;
        qa[r][0] = *(const uint32_t*)(sm + SM_Q + row       * KPITCH + 4 * q);
        qa[r][1] = *(const uint32_t*)(sm + SM_Q + (row + 8) * KPITCH + 4 * q);
        qa[r][2] = *(const uint32_t*)(sm + SM_Q + row       * KPITCH + 16 + 4 * q);
        qa[r][3] = *(const uint32_t*)(sm + SM_Q + (row + 8) * KPITCH + 16 + 4 * q);
    }

    float o[2][16][4];
#pragma unroll
    for (int r = 0; r < 2; ++r)
#pragma unroll
        for (int jc = 0; jc < 16; ++jc)
#pragma unroll
            for (int k = 0; k < 4; ++k) o[r][jc][k] = 0.f;
    float l00 = 0.f, l01 = 0.f, l10 = 0.f, l11 = 0.f;

    for (int t = 0; t < NTILES; ++t) {
        if (t + 1 < NTILES) {
            issue_tile(smb, kg, vg, t + 1, (t + 1) & 1, tid);
            CP_COMMIT();
            CP_WAIT(1);
        } else {
            CP_WAIT(0);
        }
        __syncthreads();

        const char* smK = sm + ((t & 1) ? SM_K1 : SM_K0);
        const char* smV = sm + ((t & 1) ? SM_V1 : SM_V0);

#pragma unroll
        for (int s = 0; s < 8; ++s) {
            // ---- K fragments (shared by both row blocks) ----
            const char* kr0 = smK + (16 * s + p)     * KPITCH + 4 * q;
            const char* kr1 = smK + (16 * s + 8 + p) * KPITCH + 4 * q;
            const uint32_t bka0 = *(const uint32_t*)(kr0);
            const uint32_t bka1 = *(const uint32_t*)(kr0 + 16);
            const uint32_t bkb0 = *(const uint32_t*)(kr1);
            const uint32_t bkb1 = *(const uint32_t*)(kr1 + 16);

            uint32_t pa[2][4];
#pragma unroll
            for (int r = 0; r < 2; ++r) {
                float d[8];
                mma16816(d,     qa[r][0], qa[r][1], qa[r][2], qa[r][3],
                         bka0, bka1, 0.f, 0.f, 0.f, 0.f);
                mma16816(d + 4, qa[r][0], qa[r][1], qa[r][2], qa[r][3],
                         bkb0, bkb1, 0.f, 0.f, 0.f, 0.f);

                const float e0 = __expf(d[0]), e1 = __expf(d[1]);
                const float e2 = __expf(d[2]), e3 = __expf(d[3]);
                const float e4 = __expf(d[4]), e5 = __expf(d[5]);
                const float e6 = __expf(d[6]), e7 = __expf(d[7]);
                if (r == 0) { l00 += (e0+e1)+(e4+e5); l01 += (e2+e3)+(e6+e7); }
                else        { l10 += (e0+e1)+(e4+e5); l11 += (e2+e3)+(e6+e7); }
                pa[r][0] = pack_bf2(e0, e1);
                pa[r][1] = pack_bf2(e2, e3);
                pa[r][2] = pack_bf2(e4, e5);
                pa[r][3] = pack_bf2(e6, e7);
            }

            // ---- MMA2: both row blocks share each V fragment ----
#pragma unroll
            for (int jc = 0; jc < 16; ++jc) {
                const char* vr = smV + (8 * jc + p) * VPITCH + 32 * s + 4 * q;
                const uint32_t bv0 = *(const uint32_t*)(vr);
                const uint32_t bv1 = *(const uint32_t*)(vr + 16);
                mma16816(o[0][jc], pa[0][0], pa[0][1], pa[0][2], pa[0][3],
                         bv0, bv1, o[0][jc][0], o[0][jc][1], o[0][jc][2], o[0][jc][3]);
                mma16816(o[1][jc], pa[1][0], pa[1][1], pa[1][2], pa[1][3],
                         bv0, bv1, o[1][jc][0], o[1][jc][1], o[1][jc][2], o[1][jc][3]);
            }
        }
        __syncthreads();
    }

    // ---- denominators: reduce over 4 q-lanes per row group ----
    l00 += __shfl_xor_sync(0xffffffffu, l00, 1);
    l00 += __shfl_xor_sync(0xffffffffu, l00, 2);
    l01 += __shfl_xor_sync(0xffffffffu, l01, 1);
    l01 += __shfl_xor_sync(0xffffffffu, l01, 2);
    l10 += __shfl_xor_sync(0xffffffffu, l10, 1);
    l10 += __shfl_xor_sync(0xffffffffu, l10, 2);
    l11 += __shfl_xor_sync(0xffffffffu, l11, 1);
    l11 += __shfl_xor_sync(0xffffffffu, l11, 2);
    const float inv[2][2] = {{1.f / l00, 1.f / l01}, {1.f / l10, 1.f / l11}};

    // ---- epilogue: out[b][c][n] = gamma * O/l + x ----
    const float g = __ldg(gamma);
#pragma unroll
    for (int r = 0; r < 2; ++r) {
        const int nrow = n0 + 32 * w + 16 * r + p;
#pragma unroll
        for (int jc = 0; jc < 16; ++jc) {
            const int c = 8 * jc + 2 * q;
            const size_t i0 = ((size_t)b * CC + c) * NN + nrow;
            out[i0]          = g * (o[r][jc][0] * inv[r][0]) + x[i0];
            out[i0 + NN]     = g * (o[r][jc][1] * inv[r][0]) + x[i0 + NN];
            out[i0 + 8]      = g * (o[r][jc][2] * inv[r][1]) + x[i0 + 8];
            out[i0 + NN + 8] = g * (o[r][jc][3] * inv[r][1]) + x[i0 + NN + 8];
        }
    }
}

// ---------------------------------------------------------------------------
// Launch
// ---------------------------------------------------------------------------
extern "C" void kernel_launch(void* const* d_in, const int* in_sizes, int n_in,
                              void* d_out, int out_size)
{
    const float* x     = (const float*)d_in[0];
    const float* wq    = (const float*)d_in[1];
    const float* bq    = (const float*)d_in[2];
    const float* wk    = (const float*)d_in[3];
    const float* bk    = (const float*)d_in[4];
    const float* wv    = (const float*)d_in[5];
    const float* bv    = (const float*)d_in[6];
    const float* gamma = (const float*)d_in[7];
    float* out = (float*)d_out;
    (void)in_sizes; (void)n_in; (void)out_size;

    qk_kernel<<<dim3(NN / 128, BB), 256>>>(x, wq, bq, wk, bk);

    cudaFuncSetAttribute(v_kernel,
                         cudaFuncAttributeMaxDynamicSharedMemorySize, VG_SMEM);
    v_kernel<<<dim3(NN / 128, BB), 256, VG_SMEM>>>(x, wv, bv);

    cudaFuncSetAttribute(attn_kernel,
                         cudaFuncAttributeMaxDynamicSharedMemorySize, SM_TOTAL);
    attn_kernel<<<dim3(NN / TQ, BB), 128, SM_TOTAL>>>(x, gamma, out);
}

// round 8
// speedup vs baseline: 1.3658x; 1.3658x over previous
#include <cuda_runtime.h>
#include <cuda_bf16.h>
#include <cstdint>
#include <cstddef>

// Problem constants
#define BB 4
#define CC 128
#define NN 4096      // H*W
#define CQ 16
#define TQ 128       // queries per CTA
#define TK 128       // keys per tile
#define NTILES (NN / TK)   // 32

// ---------------------------------------------------------------------------
// Device scratch (bf16 QKV staged between kernels)
// ---------------------------------------------------------------------------
__device__ __align__(16) __nv_bfloat16 g_qb[(size_t)BB * NN * CQ];  // [b][n][cq]
__device__ __align__(16) __nv_bfloat16 g_kb[(size_t)BB * NN * CQ];  // [b][n][cq]
__device__ __align__(16) __nv_bfloat16 g_vb[(size_t)BB * CC * NN];  // [b][c][n]

// ---------------------------------------------------------------------------
// Helpers
// ---------------------------------------------------------------------------
__device__ __forceinline__ uint32_t smem_u32(const void* p) {
    uint32_t a;
    asm("{ .reg .u64 t; cvta.to.shared.u64 t, %1; cvt.u32.u64 %0, t; }"
        : "=r"(a) : "l"(p));
    return a;
}
// pack two fp32 -> bf16x2 (lo in low half)
__device__ __forceinline__ uint32_t pack_bf2(float lo, float hi) {
    uint32_t r;
    asm("cvt.rn.satfinite.bf16x2.f32 %0, %1, %2;" : "=r"(r) : "f"(hi), "f"(lo));
    return r;
}
__device__ __forceinline__ void cp16(uint32_t dst, const void* src) {
    asm volatile("cp.async.cg.shared.global [%0], [%1], 16;"
                 :: "r"(dst), "l"(src));
}
#define CP_COMMIT() asm volatile("cp.async.commit_group;" ::: "memory")
#define CP_WAIT(n)  asm volatile("cp.async.wait_group %0;" :: "n"(n) : "memory")

// mma.m16n8k16 bf16 -> fp32
__device__ __forceinline__ void mma16816(
    float* d,
    uint32_t a0, uint32_t a1, uint32_t a2, uint32_t a3,
    uint32_t b0, uint32_t b1,
    float c0, float c1, float c2, float c3)
{
    asm volatile(
        "mma.sync.aligned.m16n8k16.row.col.f32.bf16.bf16.f32 "
        "{%0,%1,%2,%3}, {%4,%5,%6,%7}, {%8,%9}, {%10,%11,%12,%13};"
        : "=f"(d[0]), "=f"(d[1]), "=f"(d[2]), "=f"(d[3])
        : "r"(a0), "r"(a1), "r"(a2), "r"(a3),
          "r"(b0), "r"(b1),
          "f"(c0), "f"(c1), "f"(c2), "f"(c3));
}

// ---------------------------------------------------------------------------
// Kernel 1: fused QKV 1x1 convs as one smem-tiled GEMM.
// Out tile per CTA: 160 rows (16 q + 16 k + 128 v) x 128 n.
// W_v staged transposed [k][c] (pitch 132, 16B aligned; reads broadcast).
// W_qk staged transposed [k][32]. x double-buffered via cp.async, k-steps 16.
// Thread (ti, tj): 8c x 8n of V plus 2 qk-rows x 8n.
// grid (32, 4), block 256.
// smem: 128*132*4 + 128*32*4 + 2*16*128*4 = 100352 B.
// ---------------------------------------------------------------------------
#define WPITCH 132
#define QKV_SMEM (128 * WPITCH * 4 + 128 * 32 * 4 + 2 * 16 * 128 * 4)

__global__ void __launch_bounds__(256, 1) qkv_kernel(
    const float* __restrict__ x,
    const float* __restrict__ wq, const float* __restrict__ bq,
    const float* __restrict__ wk, const float* __restrict__ bk,
    const float* __restrict__ wv, const float* __restrict__ bv)
{
    extern __shared__ float s[];
    float* w_st  = s;                       // [128 k][WPITCH]
    float* wqk   = s + 128 * WPITCH;        // [128 k][32]  (q rows 0-15, k rows 16-31)
    float* x_s   = wqk + 128 * 32;          // [2][16][128]
    const uint32_t xsb = smem_u32(x_s);

    const int tid = threadIdx.x;
    const int b   = blockIdx.y;
    const int n0  = blockIdx.x * 128;
    const int ti  = tid & 15;               // n group
    const int tj  = tid >> 4;               // c group
    const int c0  = tj * 8;
    const int nb  = ti * 8;
    const int r0  = tj * 2;                 // qk row pair

    // stage Wv transposed: w_st[k][c] = wv[c][k]
    for (int i = tid; i < CC * CC; i += 256) {
        const int c = i >> 7, k = i & 127;
        w_st[k * WPITCH + c] = wv[i];
    }
    // stage Wq/Wk transposed: wqk[k][r] = wq[r][k], wqk[k][16+r] = wk[r][k]
    for (int i = tid; i < CQ * CC; i += 256) {
        const int r = i >> 7, k = i & 127;
        wqk[k * 32 + r]      = wq[i];
        wqk[k * 32 + 16 + r] = wk[i];
    }

    const float* xb = x + (size_t)b * CC * NN + n0;

    // stage x k-block 0
#pragma unroll
    for (int it = 0; it < 2; ++it) {
        const int i = tid + it * 256;
        const int r = i >> 5, cc = (i & 31) * 4;
        cp16(xsb + (uint32_t)(r * 128 + cc) * 4, xb + (size_t)r * NN + cc);
    }
    CP_COMMIT();

    float acc[8][8];
    float qkacc[2][8];
#pragma unroll
    for (int j = 0; j < 8; ++j) {
        qkacc[0][j] = 0.f; qkacc[1][j] = 0.f;
#pragma unroll
        for (int k = 0; k < 8; ++k) acc[j][k] = 0.f;
    }

    for (int t = 0; t < 8; ++t) {
        if (t + 1 < 8) {
            const uint32_t dst = xsb + (uint32_t)(((t + 1) & 1) * 2048) * 4;
#pragma unroll
            for (int it = 0; it < 2; ++it) {
                const int i = tid + it * 256;
                const int r = i >> 5, cc = (i & 31) * 4;
                cp16(dst + (uint32_t)(r * 128 + cc) * 4,
                     xb + (size_t)(16 * (t + 1) + r) * NN + cc);
            }
            CP_COMMIT();
            CP_WAIT(1);
        } else {
            CP_WAIT(0);
        }
        __syncthreads();

        const float* xs   = x_s + (t & 1) * 2048;
        const float* wkp  = w_st + 16 * t * WPITCH;
        const float* wqkp = wqk + 16 * t * 32;
#pragma unroll
        for (int kk = 0; kk < 16; ++kk) {
            const float4 w0 = *(const float4*)(wkp + kk * WPITCH + c0);
            const float4 w1 = *(const float4*)(wkp + kk * WPITCH + c0 + 4);
            const float  u0 = wqkp[kk * 32 + r0];
            const float  u1 = wqkp[kk * 32 + r0 + 1];
            const float4 x0 = *(const float4*)(xs + kk * 128 + nb);
            const float4 x1 = *(const float4*)(xs + kk * 128 + nb + 4);
            const float wr[8] = {w0.x, w0.y, w0.z, w0.w, w1.x, w1.y, w1.z, w1.w};
            const float xr[8] = {x0.x, x0.y, x0.z, x0.w, x1.x, x1.y, x1.z, x1.w};
#pragma unroll
            for (int k = 0; k < 8; ++k) {
                qkacc[0][k] += u0 * xr[k];
                qkacc[1][k] += u1 * xr[k];
#pragma unroll
                for (int j = 0; j < 8; ++j)
                    acc[j][k] += wr[j] * xr[k];
            }
        }
        __syncthreads();
    }

    // ---- V epilogue: bias, pack bf16, store [c][n] ----
#pragma unroll
    for (int j = 0; j < 8; ++j) {
        const float bb = bv[c0 + j];
        uint4 u;
        u.x = pack_bf2(acc[j][0] + bb, acc[j][1] + bb);
        u.y = pack_bf2(acc[j][2] + bb, acc[j][3] + bb);
        u.z = pack_bf2(acc[j][4] + bb, acc[j][5] + bb);
        u.w = pack_bf2(acc[j][6] + bb, acc[j][7] + bb);
        *(uint4*)((char*)g_vb + (((size_t)b * CC + c0 + j) * NN + n0 + nb) * 2) = u;
    }

    // ---- QK epilogue: transpose 32x128 through smem (reuse x_s), pack [n][16] ----
    {
        const float bias0 = (r0 < 16) ? __ldg(bq + r0) : __ldg(bk + r0 - 16);
        const float bias1 = (r0 + 1 < 16) ? __ldg(bq + r0 + 1) : __ldg(bk + r0 - 15);
        float* qk_s = x_s;                  // [32 rows][128 n] = 4096 floats
#pragma unroll
        for (int k = 0; k < 8; ++k) {
            qk_s[r0 * 128 + nb + k]       = qkacc[0][k] + bias0;
            qk_s[(r0 + 1) * 128 + nb + k] = qkacc[1][k] + bias1;
        }
        __syncthreads();

        const int half = tid >> 7;          // 0: q, 1: k
        const int nl   = tid & 127;
        const int rb   = half * 16;
        uint32_t pk[8];
#pragma unroll
        for (int j = 0; j < 8; ++j)
            pk[j] = pack_bf2(qk_s[(rb + 2 * j) * 128 + nl],
                             qk_s[(rb + 2 * j + 1) * 128 + nl]);
        char* dst = (char*)(half ? g_kb : g_qb) + ((size_t)b * NN + n0 + nl) * 32;
        *(uint4*)(dst)      = make_uint4(pk[0], pk[1], pk[2], pk[3]);
        *(uint4*)(dst + 16) = make_uint4(pk[4], pk[5], pk[6], pk[7]);
    }
}

// ---------------------------------------------------------------------------
// Kernel 2: HMMA flash attention (R5 shape: 8 warps x 16 queries).
// grid (32, 4), 256 threads; warp w owns queries [16w, 16w+16).
// smem: Q [128][48] 6144 | K0/K1 6144 | V0/V1 [128c][272] 34816 ea. 88064 B.
// ---------------------------------------------------------------------------
#define KPITCH 48
#define VPITCH 272
#define SM_Q   0
#define SM_K0  6144
#define SM_K1  12288
#define SM_V0  18432
#define SM_V1  (SM_V0 + 34816)
#define SM_TOTAL (SM_V1 + 34816)

__device__ __forceinline__ void issue_tile(
    uint32_t smb, const char* kg, const char* vg, int t, int buf, int tid)
{
    const uint32_t kdst = smb + (buf ? SM_K1 : SM_K0);
    const uint32_t vdst = smb + (buf ? SM_V1 : SM_V0);
    const int m0 = t * TK;
    {   // K tile: 128 rows x 32B = 256 x 16B chunks
        const int n = tid >> 1, h = tid & 1;
        cp16(kdst + n * KPITCH + h * 16, kg + (size_t)(m0 + n) * 32 + h * 16);
    }
    // V tile: 128 rows x 256B = 2048 x 16B chunks
#pragma unroll
    for (int it = 0; it < 8; ++it) {
        const int i = tid + it * 256;
        const int c = i >> 4, h = i & 15;
        cp16(vdst + c * VPITCH + h * 16,
             vg + (size_t)c * (NN * 2) + (size_t)m0 * 2 + h * 16);
    }
}

__global__ void __launch_bounds__(256, 1) attn_kernel(
    const float* __restrict__ x,
    const float* __restrict__ gamma,
    float* __restrict__ out)
{
    extern __shared__ char sm[];
    const uint32_t smb = smem_u32(sm);
    const int tid  = threadIdx.x;
    const int w    = tid >> 5;
    const int lane = tid & 31;
    const int p    = lane >> 2;      // row group
    const int q    = lane & 3;       // col pair

    const int b  = blockIdx.y;
    const int n0 = blockIdx.x * TQ;

    const char* qg = (const char*)g_qb + ((size_t)b * NN + n0) * 32;
    const char* kg = (const char*)g_kb + (size_t)b * NN * 32;
    const char* vg = (const char*)g_vb + (size_t)b * CC * NN * 2;

    // ---- load Q tile (plain), issue K/V tile 0 (cp.async) ----
    {
        const int r = tid >> 1, h = tid & 1;
        *(uint4*)(sm + SM_Q + r * KPITCH + h * 16) =
            *(const uint4*)(qg + r * 32 + h * 16);
    }
    issue_tile(smb, kg, vg, 0, 0, tid);
    CP_COMMIT();
    __syncthreads();

    // ---- Q A-fragments (held in registers for the whole kernel) ----
    uint32_t qa0, qa1, qa2, qa3;
    {
        const int r = 16 * w + p;
        qa0 = *(const uint32_t*)(sm + SM_Q + r       * KPITCH + 4 * q);
        qa1 = *(const uint32_t*)(sm + SM_Q + (r + 8) * KPITCH + 4 * q);
        qa2 = *(const uint32_t*)(sm + SM_Q + r       * KPITCH + 16 + 4 * q);
        qa3 = *(const uint32_t*)(sm + SM_Q + (r + 8) * KPITCH + 16 + 4 * q);
    }

    float o[16][4];
#pragma unroll
    for (int jc = 0; jc < 16; ++jc)
#pragma unroll
        for (int k = 0; k < 4; ++k) o[jc][k] = 0.f;
    float l0 = 0.f, l1 = 0.f;

    for (int t = 0; t < NTILES; ++t) {
        if (t + 1 < NTILES) {
            issue_tile(smb, kg, vg, t + 1, (t + 1) & 1, tid);
            CP_COMMIT();
            CP_WAIT(1);
        } else {
            CP_WAIT(0);
        }
        __syncthreads();

        const char* smK = sm + ((t & 1) ? SM_K1 : SM_K0);
        const char* smV = sm + ((t & 1) ? SM_V1 : SM_V0);

#pragma unroll
        for (int s = 0; s < 8; ++s) {
            // ---- MMA1: S tiles j=2s, 2s+1 (keys 16s..16s+15) ----
            const char* kr0 = smK + (16 * s + p)     * KPITCH + 4 * q;
            const char* kr1 = smK + (16 * s + 8 + p) * KPITCH + 4 * q;
            const uint32_t bka0 = *(const uint32_t*)(kr0);
            const uint32_t bka1 = *(const uint32_t*)(kr0 + 16);
            const uint32_t bkb0 = *(const uint32_t*)(kr1);
            const uint32_t bkb1 = *(const uint32_t*)(kr1 + 16);

            float d[8];
            mma16816(d,     qa0, qa1, qa2, qa3, bka0, bka1, 0.f, 0.f, 0.f, 0.f);
            mma16816(d + 4, qa0, qa1, qa2, qa3, bkb0, bkb1, 0.f, 0.f, 0.f, 0.f);

            // ---- exp (no max subtraction; scores bounded) ----
            const float e0 = __expf(d[0]), e1 = __expf(d[1]);
            const float e2 = __expf(d[2]), e3 = __expf(d[3]);
            const float e4 = __expf(d[4]), e5 = __expf(d[5]);
            const float e6 = __expf(d[6]), e7 = __expf(d[7]);
            l0 += (e0 + e1) + (e4 + e5);
            l1 += (e2 + e3) + (e6 + e7);

            // D-fragments of tile pair == A-fragment of k16 step (FA trick)
            const uint32_t pa0 = pack_bf2(e0, e1);
            const uint32_t pa1 = pack_bf2(e2, e3);
            const uint32_t pa2 = pack_bf2(e4, e5);
            const uint32_t pa3 = pack_bf2(e6, e7);

            // ---- MMA2: O[16q x 128c] += P * V^T over keys 16s..16s+15 ----
#pragma unroll
            for (int jc = 0; jc < 16; ++jc) {
                const char* vr = smV + (8 * jc + p) * VPITCH + 32 * s + 4 * q;
                const uint32_t bv0 = *(const uint32_t*)(vr);
                const uint32_t bv1 = *(const uint32_t*)(vr + 16);
                mma16816(o[jc], pa0, pa1, pa2, pa3, bv0, bv1,
                         o[jc][0], o[jc][1], o[jc][2], o[jc][3]);
            }
        }
        __syncthreads();
    }

    // ---- softmax denominators: reduce over the 4 lanes of each row group ----
    l0 += __shfl_xor_sync(0xffffffffu, l0, 1);
    l0 += __shfl_xor_sync(0xffffffffu, l0, 2);
    l1 += __shfl_xor_sync(0xffffffffu, l1, 1);
    l1 += __shfl_xor_sync(0xffffffffu, l1, 2);
    const float inv0 = 1.f / l0;
    const float inv1 = 1.f / l1;

    // ---- epilogue: out[b][c][n] = gamma * O/l + x ----
    const float g = __ldg(gamma);
    const int nrow = n0 + 16 * w + p;
#pragma unroll
    for (int jc = 0; jc < 16; ++jc) {
        const int c = 8 * jc + 2 * q;
        const size_t i0 = ((size_t)b * CC + c) * NN + nrow;
        out[i0]          = g * (o[jc][0] * inv0) + x[i0];
        out[i0 + NN]     = g * (o[jc][1] * inv0) + x[i0 + NN];
        out[i0 + 8]      = g * (o[jc][2] * inv1) + x[i0 + 8];
        out[i0 + NN + 8] = g * (o[jc][3] * inv1) + x[i0 + NN + 8];
    }
}

// ---------------------------------------------------------------------------
// Launch
// ---------------------------------------------------------------------------
extern "C" void kernel_launch(void* const* d_in, const int* in_sizes, int n_in,
                              void* d_out, int out_size)
{
    const float* x     = (const float*)d_in[0];
    const float* wq    = (const float*)d_in[1];
    const float* bq    = (const float*)d_in[2];
    const float* wk    = (const float*)d_in[3];
    const float* bk    = (const float*)d_in[4];
    const float* wv    = (const float*)d_in[5];
    const float* bv    = (const float*)d_in[6];
    const float* gamma = (const float*)d_in[7];
    float* out = (float*)d_out;
    (void)in_sizes; (void)n_in; (void)out_size;

    cudaFuncSetAttribute(qkv_kernel,
                         cudaFuncAttributeMaxDynamicSharedMemorySize, QKV_SMEM);
    qkv_kernel<<<dim3(NN / 128, BB), 256, QKV_SMEM>>>(x, wq, bq, wk, bk, wv, bv);

    cudaFuncSetAttribute(attn_kernel,
                         cudaFuncAttributeMaxDynamicSharedMemorySize, SM_TOTAL);
    attn_kernel<<<dim3(NN / TQ, BB), 256, SM_TOTAL>>>(x, gamma, out);
}